// round 17
// baseline (speedup 1.0000x reference)
#include <cuda_runtime.h>
#include <cuda_bf16.h>
#include <math.h>
#include <stdint.h>

#define Bb 8
#define Nn 2048
#define Ee 32
#define Hc 128
#define Sc 256
#define Tt 12
#define NEL (Bb*Ee*Nn)
#define ALPHA 0.05f
#define EPSV 1e-5f
#define AP 72   // spmm smem pitch bf16 (144B)
#define CP 24   // conv smem pitch bf16 (48B)

typedef unsigned long long u64;
typedef __nv_bfloat16 bf16;

// ---------------- packed fp32x2 helpers ----------------
__device__ __forceinline__ u64 splat2(float a) {
    u64 d; asm("mov.b64 %0, {%1, %1};" : "=l"(d) : "f"(a)); return d;
}
__device__ __forceinline__ void upk2(u64 v, float& lo, float& hi) {
    asm("mov.b64 {%0, %1}, %2;" : "=f"(lo), "=f"(hi) : "l"(v));
}
__device__ __forceinline__ u64 fma2(u64 a, u64 b, u64 c) {
    u64 d; asm("fma.rn.f32x2 %0, %1, %2, %3;" : "=l"(d) : "l"(a), "l"(b), "l"(c)); return d;
}

// ---------------- warp-level bf16 MMA + ldmatrix ----------------
__device__ __forceinline__ void hmma(float4& d, uint32_t a0, uint32_t a1, uint32_t a2,
                                     uint32_t a3, uint32_t b0, uint32_t b1) {
    asm volatile(
        "mma.sync.aligned.m16n8k16.row.col.f32.bf16.bf16.f32 "
        "{%0,%1,%2,%3}, {%4,%5,%6,%7}, {%8,%9}, {%0,%1,%2,%3};"
        : "+f"(d.x), "+f"(d.y), "+f"(d.z), "+f"(d.w)
        : "r"(a0), "r"(a1), "r"(a2), "r"(a3), "r"(b0), "r"(b1));
}
__device__ __forceinline__ void ldm4(uint32_t& r0, uint32_t& r1, uint32_t& r2, uint32_t& r3,
                                     uint32_t addr) {
    asm volatile("ldmatrix.sync.aligned.m8n8.x4.shared.b16 {%0,%1,%2,%3}, [%4];"
        : "=r"(r0), "=r"(r1), "=r"(r2), "=r"(r3) : "r"(addr));
}
__device__ __forceinline__ void ldm4t(uint32_t& r0, uint32_t& r1, uint32_t& r2, uint32_t& r3,
                                      uint32_t addr) {
    asm volatile("ldmatrix.sync.aligned.m8n8.x4.trans.shared.b16 {%0,%1,%2,%3}, [%4];"
        : "=r"(r0), "=r"(r1), "=r"(r2), "=r"(r3) : "r"(addr));
}
__device__ __forceinline__ uint32_t smem_u32(const void* p) {
    uint32_t a;
    asm("{ .reg .u64 t; cvta.to.shared.u64 t, %1; cvt.u32.u64 %0, t; }" : "=r"(a) : "l"(p));
    return a;
}

// ---------------- device scratch ----------------
__device__ float g_x[NEL];
__device__ float g_xacc[NEL];
__device__ float g_h1g[3][NEL];
__device__ float g_h2g[3][NEL];
__device__ float g_skip[Bb*Sc*Nn];
__device__ float g_rs_s[Nn];
__device__ float g_rs_d[Bb*Nn];
__device__ float g_cs_d[Bb*Nn];
__device__ float g_redL[3][Bb*2];
__device__ bf16 g_Ahi[Bb*Nn*Nn];   // stores A + I
__device__ bf16 g_Shi[Nn*Nn];      // stores S + I
__device__ bf16 g_sxHi[NEL];
__device__ bf16 g_s1Hi[3][NEL];
// transposed-split activations [b][n][128]
__device__ bf16 g_in1Th[Bb*Nn*Hc];
__device__ bf16 g_in1Tl[Bb*Nn*Hc];
__device__ bf16 g_hidTh[Bb*Nn*Hc];
__device__ bf16 g_hidTl[Bb*Nn*Hc];
__device__ bf16 g_hid2Th[Bb*Nn*Hc];
__device__ bf16 g_hid2Tl[Bb*Nn*Hc];
// split weights
__device__ bf16 g_eWfh[6*Hc*Hc];
__device__ bf16 g_eWfl[6*Hc*Hc];
__device__ bf16 g_eWgh[6*Hc*Hc];
__device__ bf16 g_eWgl[6*Hc*Hc];
__device__ bf16 g_skWh[3*Sc*Hc];
__device__ bf16 g_skWl[3*Sc*Hc];
// combined mixprop mlp weights
__device__ float g_gWc[3*32*224];
__device__ float g_gbc[96];

struct Srcs { const float* p[8]; };
struct SpmmB {
    const bf16* A[3];
    u64 abst[3];
    const float* den[3];
    int denB[3];
    const bf16* H[3];
    float* hout[3];
    bf16* sOut[3];
    int writeSplit;
};
struct GatedP {
    const bf16 *inTh, *inTl, *Wfh, *Wfl, *Wgh, *Wgl;
    const float *bf_, *bg_;
    bf16 *outTh, *outTl;
};
struct SkipP {
    const bf16 *inTh, *inTl, *Wh, *Wl;
    const float* bias;
    float* out;
    int accFlag;
};
struct ConvP {
    Srcs srcs;
    int inBStride;
    const float *W, *bias;
    int M, K;
    float* out;
    int outBStride;
    int accFlag;
    const float* iden;
    float* redOut;
};

__device__ __forceinline__ void bsplit(float a, bf16& h, bf16& l) {
    h = __float2bfloat16(a);
    l = __float2bfloat16(a - __bfloat162float(h));
}
__device__ __forceinline__ uint32_t bpack(bf16 a, bf16 b) {
    __nv_bfloat162 t; t.x = a; t.y = b;
    return *reinterpret_cast<uint32_t*>(&t);
}

// ---------------- helpers ----------------
__device__ __forceinline__ float blockReduceSum(float v) {
    __shared__ float sh[32];
    int lane = threadIdx.x & 31, wid = threadIdx.x >> 5;
    #pragma unroll
    for (int o = 16; o; o >>= 1) v += __shfl_down_sync(0xffffffffu, v, o);
    __syncthreads();
    if (lane == 0) sh[wid] = v;
    __syncthreads();
    int nw = blockDim.x >> 5;
    v = (threadIdx.x < nw) ? sh[threadIdx.x] : 0.f;
    if (wid == 0) {
        #pragma unroll
        for (int o = 16; o; o >>= 1) v += __shfl_down_sync(0xffffffffu, v, o);
    }
    return v;
}

__global__ void copy_split_k(float* __restrict__ dst, const float* __restrict__ src) {
    int i = blockIdx.x * 256 + threadIdx.x;
    if (i >= NEL / 4) return;
    float4 a = ((const float4*)src)[i];
    ((float4*)dst)[i] = a;
    bf16 h[4], l[4];
    bsplit(a.x, h[0], l[0]); bsplit(a.y, h[1], l[1]);
    bsplit(a.z, h[2], l[2]); bsplit(a.w, h[3], l[3]);
    ((uint2*)g_sxHi)[i] = make_uint2(bpack(h[0], h[1]), bpack(h[2], h[3]));
    int n4 = i % (Nn / 4);
    int c  = (i / (Nn / 4)) % Ee;
    int b  = i / (Ee * Nn / 4);
    size_t base = ((size_t)b * Nn + n4 * 4) * Hc + c;
    #pragma unroll
    for (int u = 0; u < 4; u++) {
        g_in1Th[base + (size_t)u * Hc] = h[u];
        g_in1Tl[base + (size_t)u * Hc] = l[u];
    }
}

// ---------------- fused prep ----------------
__global__ void init_den_k() {
    int i = blockIdx.x * 256 + threadIdx.x;
    if (i < Nn) g_rs_s[i] = 1.0f;
    if (i < Bb * Nn) { g_rs_d[i] = 1.0f; g_cs_d[i] = 1.0f; }
    if (i < 3 * Bb * 2) ((float*)g_redL)[i] = 0.f;
}

__global__ void prepA_k(const float* __restrict__ A) {
    __shared__ float sh[64][68];
    const int b = blockIdx.z;
    const int r0 = blockIdx.x * 64, c0 = blockIdx.y * 64;
    const int tid = threadIdx.x;
    const int row = tid >> 2, q = tid & 3;

    const float* Ab = A + (size_t)b * Nn * Nn;
    float rsum = 0.f;
    #pragma unroll
    for (int j = 0; j < 4; j++) {
        int idx4 = q + j * 4;
        float4 v = *(const float4*)&Ab[(size_t)(r0 + row) * Nn + c0 + idx4 * 4];
        *(float4*)&sh[row][idx4 * 4] = v;
        rsum += v.x + v.y + v.z + v.w;
        int gr = r0 + row, gc = c0 + idx4 * 4;
        float vv[4] = {v.x, v.y, v.z, v.w};
        #pragma unroll
        for (int u = 0; u < 4; u++) if (gr == gc + u) vv[u] += 1.0f;
        bf16 h0 = __float2bfloat16(vv[0]), h1 = __float2bfloat16(vv[1]);
        bf16 h2 = __float2bfloat16(vv[2]), h3 = __float2bfloat16(vv[3]);
        size_t o = ((size_t)b * Nn + gr) * Nn + gc;
        *(uint2*)&g_Ahi[o] = make_uint2(bpack(h0, h1), bpack(h2, h3));
    }
    rsum += __shfl_down_sync(0xffffffffu, rsum, 1);
    rsum += __shfl_down_sync(0xffffffffu, rsum, 2);
    if (q == 0) atomicAdd(&g_rs_d[b * Nn + r0 + row], rsum);
    __syncthreads();
    float csum = 0.f;
    #pragma unroll
    for (int j = 0; j < 4; j++) {
        int idx4 = q + j * 4;
        csum += sh[idx4 * 4 + 0][row] + sh[idx4 * 4 + 1][row]
              + sh[idx4 * 4 + 2][row] + sh[idx4 * 4 + 3][row];
    }
    csum += __shfl_down_sync(0xffffffffu, csum, 1);
    csum += __shfl_down_sync(0xffffffffu, csum, 2);
    if (q == 0) atomicAdd(&g_cs_d[b * Nn + c0 + row], csum);
}

__global__ void prepS_k(const float* __restrict__ S) {
    const int r0 = blockIdx.x * 64, c0 = blockIdx.y * 64;
    const int tid = threadIdx.x;
    const int row = tid >> 2, q = tid & 3;
    float rsum = 0.f;
    #pragma unroll
    for (int j = 0; j < 4; j++) {
        int idx4 = q + j * 4;
        float4 v = *(const float4*)&S[(size_t)(r0 + row) * Nn + c0 + idx4 * 4];
        rsum += v.x + v.y + v.z + v.w;
        int gr = r0 + row, gc = c0 + idx4 * 4;
        float vv[4] = {v.x, v.y, v.z, v.w};
        #pragma unroll
        for (int u = 0; u < 4; u++) if (gr == gc + u) vv[u] += 1.0f;
        bf16 h0 = __float2bfloat16(vv[0]), h1 = __float2bfloat16(vv[1]);
        bf16 h2 = __float2bfloat16(vv[2]), h3 = __float2bfloat16(vv[3]);
        size_t o = (size_t)gr * Nn + gc;
        *(uint2*)&g_Shi[o] = make_uint2(bpack(h0, h1), bpack(h2, h3));
    }
    rsum += __shfl_down_sync(0xffffffffu, rsum, 1);
    rsum += __shfl_down_sync(0xffffffffu, rsum, 2);
    if (q == 0) atomicAdd(&g_rs_s[r0 + row], rsum);
}

__global__ void cvt_k(const float* __restrict__ A, bf16* __restrict__ hi,
                      bf16* __restrict__ lo, int n4) {
    int i = blockIdx.x * 256 + threadIdx.x;
    if (i >= n4) return;
    float4 a = ((const float4*)A)[i];
    bf16 h0, h1, h2, h3, l0, l1, l2, l3;
    bsplit(a.x, h0, l0); bsplit(a.y, h1, l1); bsplit(a.z, h2, l2); bsplit(a.w, h3, l3);
    ((uint2*)hi)[i] = make_uint2(bpack(h0, h1), bpack(h2, h3));
    ((uint2*)lo)[i] = make_uint2(bpack(l0, l1), bpack(l2, l3));
}

__global__ void embT_k(const float* __restrict__ spE, const float* __restrict__ tdE,
                       const float* __restrict__ twE) {
    int idx = blockIdx.x * 256 + threadIdx.x;
    if (idx >= Bb * 96 * (Nn / 4)) return;
    int n4 = idx % (Nn / 4);
    int rest = idx / (Nn / 4);
    int ch = rest % 96, b = rest / 96;
    const float* src = (ch < 32) ? spE : (ch < 64 ? tdE : twE);
    int c = ch & 31;
    float4 v = *(const float4*)(src + ((size_t)b * 32 + c) * Nn + n4 * 4);
    int oc = 32 + ch;
    float vv[4] = {v.x, v.y, v.z, v.w};
    size_t base = ((size_t)b * Nn + n4 * 4) * Hc + oc;
    #pragma unroll
    for (int u = 0; u < 4; u++) {
        bf16 h, l; bsplit(vv[u], h, l);
        g_in1Th[base + (size_t)u * Hc] = h;
        g_in1Tl[base + (size_t)u * Hc] = l;
    }
}

__global__ void combW_k(const float* __restrict__ W0, const float* __restrict__ W1,
                        const float* __restrict__ W2) {
    int idx = blockIdx.x * 256 + threadIdx.x;
    if (idx >= 3 * 32 * 224) return;
    int c = idx % 224;
    int m = (idx / 224) % 32;
    int i = idx / (224 * 32);
    const float* W[3] = {W0 + (size_t)i * 32 * 96, W1 + (size_t)i * 32 * 96, W2 + (size_t)i * 32 * 96};
    float v;
    if (c < 32) v = W[0][m * 96 + c] + W[1][m * 96 + c] + W[2][m * 96 + c];
    else {
        int t = c - 32, g = t >> 6, j = t & 63;
        v = W[g][m * 96 + 32 + j];
    }
    g_gWc[idx] = v;
}
__global__ void combB_k(const float* __restrict__ b0, const float* __restrict__ b1,
                        const float* __restrict__ b2) {
    int idx = threadIdx.x;
    if (idx < 96) g_gbc[idx] = b0[idx] + b1[idx] + b2[idx];
}

// ================= device bodies (verbatim R15 logic) =================
__device__ void spmm_dev(const SpmmB& args, int vt, int b, int gr, char* buf) {
    bf16* sAh = (bf16*)buf;
    bf16* sHh = (bf16*)(buf + 64 * AP * 2);

    const int tid = threadIdx.x, wid = tid >> 5, lane = tid & 31;
    const int g = lane >> 2, tg = lane & 3;
    const int v0 = vt * 64;
    const int warpV = (wid >> 1) * 16;
    const int c0w = (wid & 1) * 16;
    const bool isT = (gr == 2);

    const bf16* Ah = args.A[gr] + (size_t)b * args.abst[gr];
    const bf16* Hh = args.H[gr] + (size_t)b * Ee * Nn;
    const float* den = args.den[gr];
    const int denB = args.denB[gr];

    const uint32_t sAh_u = smem_u32(sAh);
    const uint32_t sHh_u = smem_u32(sHh);
    const uint32_t offA_nt = (uint32_t)((warpV + (lane & 15)) * AP + (lane >> 4) * 8) * 2;
    const uint32_t offA_t = (uint32_t)(((lane & 7) + ((lane >> 4) & 1) * 8) * AP
                                       + warpV + ((lane >> 3) & 1) * 8) * 2;
    const int rowB = c0w + (lane & 7) + ((lane >> 4) & 1) * 8;
    const int khB  = ((lane >> 3) & 1) * 8;
    const uint32_t offB = (uint32_t)(rowB * AP + khB) * 2;

    float4 acc[2] = {};

    int ar0 = tid >> 3,           au0 = tid & 7;
    int ar1 = (tid + 256) >> 3,   au1 = tid & 7;
    int hc  = tid >> 3,           hu = tid & 7;

    const bf16* pA0 = isT ? (Ah + (size_t)ar0 * Nn + v0 + au0 * 8)
                          : (Ah + (size_t)(v0 + ar0) * Nn + au0 * 8);
    const bf16* pA1 = isT ? (Ah + (size_t)ar1 * Nn + v0 + au1 * 8)
                          : (Ah + (size_t)(v0 + ar1) * Nn + au1 * 8);
    const size_t chStride = isT ? (size_t)64 * Nn : 64;

    uint4 pAh0, pAh1, pHh;
    pAh0 = *(const uint4*)pA0;
    pAh1 = *(const uint4*)pA1;
    pHh  = *(const uint4*)(Hh + (size_t)hc * Nn + hu * 8);

    for (int ch = 0; ch < 32; ch++) {
        __syncthreads();
        *(uint4*)&sAh[ar0 * AP + au0 * 8] = pAh0;
        *(uint4*)&sAh[ar1 * AP + au1 * 8] = pAh1;
        *(uint4*)&sHh[hc * AP + hu * 8] = pHh;
        if (ch < 31) {
            pA0 += chStride;
            pA1 += chStride;
            pAh0 = *(const uint4*)pA0;
            pAh1 = *(const uint4*)pA1;
            pHh  = *(const uint4*)(Hh + (size_t)hc * Nn + (ch + 1) * 64 + hu * 8);
        }
        __syncthreads();
        if (isT) {
            #pragma unroll
            for (int ks = 0; ks < 4; ks++) {
                uint32_t ah0, ah1, ah2, ah3, bh00, bh01, bh10, bh11;
                ldm4t(ah0, ah1, ah2, ah3, sAh_u + offA_t + (uint32_t)ks * 16 * AP * 2);
                ldm4(bh00, bh01, bh10, bh11, sHh_u + offB + ks * 32);
                hmma(acc[0], ah0, ah1, ah2, ah3, bh00, bh01);
                hmma(acc[1], ah0, ah1, ah2, ah3, bh10, bh11);
            }
        } else {
            #pragma unroll
            for (int ks = 0; ks < 4; ks++) {
                uint32_t ah0, ah1, ah2, ah3, bh00, bh01, bh10, bh11;
                ldm4(ah0, ah1, ah2, ah3, sAh_u + offA_nt + ks * 32);
                ldm4(bh00, bh01, bh10, bh11, sHh_u + offB + ks * 32);
                hmma(acc[0], ah0, ah1, ah2, ah3, bh00, bh01);
                hmma(acc[1], ah0, ah1, ah2, ah3, bh10, bh11);
            }
        }
    }

    const int vlo = v0 + warpV + g;
    const int vhi = vlo + 8;
    const float rd_lo = (1.0f - ALPHA) / den[denB * b + vlo];
    const float rd_hi = (1.0f - ALPHA) / den[denB * b + vhi];
    const float* xb = g_x + (size_t)b * Ee * Nn;
    float* ob = args.hout[gr] + (size_t)b * Ee * Nn;
    bf16* oh = args.sOut[gr] + (size_t)b * Ee * Nn;
    #pragma unroll
    for (int nt = 0; nt < 2; nt++) {
        int c0 = c0w + nt * 8 + 2 * tg;
        float vals[4];
        size_t idxs[4];
        idxs[0] = (size_t)c0 * Nn + vlo;
        idxs[1] = (size_t)(c0 + 1) * Nn + vlo;
        idxs[2] = (size_t)c0 * Nn + vhi;
        idxs[3] = (size_t)(c0 + 1) * Nn + vhi;
        vals[0] = ALPHA * xb[idxs[0]] + acc[nt].x * rd_lo;
        vals[1] = ALPHA * xb[idxs[1]] + acc[nt].y * rd_lo;
        vals[2] = ALPHA * xb[idxs[2]] + acc[nt].z * rd_hi;
        vals[3] = ALPHA * xb[idxs[3]] + acc[nt].w * rd_hi;
        #pragma unroll
        for (int u = 0; u < 4; u++) {
            ob[idxs[u]] = vals[u];
            if (args.writeSplit) oh[idxs[u]] = __float2bfloat16(vals[u]);
        }
    }
}

__device__ void gated_dev(const GatedP& p, int blk, char* buf) {
    bf16* sWfh = (bf16*)buf;
    bf16* sWfl = sWfh + Hc * CP;
    bf16* sWgh = sWfl + Hc * CP;
    bf16* sWgl = sWgh + Hc * CP;
    bf16* sIh  = sWgl + Hc * CP;
    bf16* sIl  = sIh + 64 * CP;

    const int tid = threadIdx.x, wid = tid >> 5, lane = tid & 31;
    const int g = lane >> 2, tg = lane & 3;
    const int col0 = blk * 64;
    const int b = col0 / Nn, n0 = col0 % Nn;
    const int warpM = wid * 16;

    const uint32_t sWfh_u = smem_u32(sWfh), sWfl_u = smem_u32(sWfl);
    const uint32_t sWgh_u = smem_u32(sWgh), sWgl_u = smem_u32(sWgl);
    const uint32_t sIh_u = smem_u32(sIh), sIl_u = smem_u32(sIl);
    const uint32_t offA = (uint32_t)((warpM + (lane & 15)) * CP + (lane >> 4) * 8) * 2;
    const uint32_t offB = (uint32_t)(((lane & 7) + ((lane >> 4) & 1) * 8) * CP
                                     + ((lane >> 3) & 1) * 8) * 2;

    float4 aF[8] = {}, aG[8] = {};

    const int wrow = tid >> 1, whalf = tid & 1;
    const int it = tid & 127, iarr = tid >> 7;
    const int irow = it >> 1, ihalf = it & 1;
    const bf16* isrc = iarr ? p.inTl : p.inTh;
    bf16* idst = iarr ? sIl : sIh;

    for (int chunk = 0; chunk < 8; chunk++) {
        const int k0 = chunk * 16;
        __syncthreads();
        size_t wg = (size_t)wrow * Hc + k0 + whalf * 8;
        *(uint4*)&sWfh[wrow * CP + whalf * 8] = *(const uint4*)(p.Wfh + wg);
        *(uint4*)&sWfl[wrow * CP + whalf * 8] = *(const uint4*)(p.Wfl + wg);
        *(uint4*)&sWgh[wrow * CP + whalf * 8] = *(const uint4*)(p.Wgh + wg);
        *(uint4*)&sWgl[wrow * CP + whalf * 8] = *(const uint4*)(p.Wgl + wg);
        *(uint4*)&idst[irow * CP + ihalf * 8] =
            *(const uint4*)(isrc + ((size_t)b * Nn + n0 + irow) * Hc + k0 + ihalf * 8);
        __syncthreads();

        uint32_t fh0, fh1, fh2, fh3, fl0, fl1, fl2, fl3;
        uint32_t gh0, gh1, gh2, gh3, gl0, gl1, gl2, gl3;
        ldm4(fh0, fh1, fh2, fh3, sWfh_u + offA);
        ldm4(fl0, fl1, fl2, fl3, sWfl_u + offA);
        ldm4(gh0, gh1, gh2, gh3, sWgh_u + offA);
        ldm4(gl0, gl1, gl2, gl3, sWgl_u + offA);
        #pragma unroll
        for (int grp = 0; grp < 4; grp++) {
            const uint32_t go = (uint32_t)(grp * 16 * CP) * 2;
            uint32_t bh0, bh1, bh2, bh3, bl0, bl1, bl2, bl3;
            ldm4(bh0, bh1, bh2, bh3, sIh_u + go + offB);
            ldm4(bl0, bl1, bl2, bl3, sIl_u + go + offB);
            hmma(aF[2*grp], fh0, fh1, fh2, fh3, bh0, bh1);
            hmma(aF[2*grp], fh0, fh1, fh2, fh3, bl0, bl1);
            hmma(aF[2*grp], fl0, fl1, fl2, fl3, bh0, bh1);
            hmma(aF[2*grp+1], fh0, fh1, fh2, fh3, bh2, bh3);
            hmma(aF[2*grp+1], fh0, fh1, fh2, fh3, bl2, bl3);
            hmma(aF[2*grp+1], fl0, fl1, fl2, fl3, bh2, bh3);
            hmma(aG[2*grp], gh0, gh1, gh2, gh3, bh0, bh1);
            hmma(aG[2*grp], gh0, gh1, gh2, gh3, bl0, bl1);
            hmma(aG[2*grp], gl0, gl1, gl2, gl3, bh0, bh1);
            hmma(aG[2*grp+1], gh0, gh1, gh2, gh3, bh2, bh3);
            hmma(aG[2*grp+1], gh0, gh1, gh2, gh3, bl2, bl3);
            hmma(aG[2*grp+1], gl0, gl1, gl2, gl3, bh2, bh3);
        }
    }

    const int m_lo = warpM + g, m_hi = m_lo + 8;
    const float bflo = p.bf_[m_lo], bfhi = p.bf_[m_hi];
    const float bglo = p.bg_[m_lo], bghi = p.bg_[m_hi];
    #pragma unroll
    for (int nt = 0; nt < 8; nt++) {
        int n = n0 + nt * 8 + 2 * tg;
        size_t r0 = ((size_t)b * Nn + n) * Hc;
        size_t r1 = r0 + Hc;
        float v0 = tanhf(aF[nt].x + bflo) * (1.f / (1.f + expf(-(aG[nt].x + bglo))));
        float v1 = tanhf(aF[nt].y + bflo) * (1.f / (1.f + expf(-(aG[nt].y + bglo))));
        float v2 = tanhf(aF[nt].z + bfhi) * (1.f / (1.f + expf(-(aG[nt].z + bghi))));
        float v3 = tanhf(aF[nt].w + bfhi) * (1.f / (1.f + expf(-(aG[nt].w + bghi))));
        bf16 h, l;
        bsplit(v0, h, l); p.outTh[r0 + m_lo] = h; p.outTl[r0 + m_lo] = l;
        bsplit(v1, h, l); p.outTh[r1 + m_lo] = h; p.outTl[r1 + m_lo] = l;
        bsplit(v2, h, l); p.outTh[r0 + m_hi] = h; p.outTl[r0 + m_hi] = l;
        bsplit(v3, h, l); p.outTh[r1 + m_hi] = h; p.outTl[r1 + m_hi] = l;
    }
}

__device__ void skip_dev(const SkipP& p, int bx, int by, char* buf) {
    bf16* sWh = (bf16*)buf;
    bf16* sWl = sWh + Hc * CP;
    bf16* sIh = sWl + Hc * CP;
    bf16* sIl = sIh + 64 * CP;

    const int tid = threadIdx.x, wid = tid >> 5, lane = tid & 31;
    const int g = lane >> 2, tg = lane & 3;
    const int col0 = bx * 64;
    const int b = col0 / Nn, n0 = col0 % Nn;
    const int mbase = by * 128;
    const int warpM = wid * 16;

    const uint32_t sWh_u = smem_u32(sWh), sWl_u = smem_u32(sWl);
    const uint32_t sIh_u = smem_u32(sIh), sIl_u = smem_u32(sIl);
    const uint32_t offA = (uint32_t)((warpM + (lane & 15)) * CP + (lane >> 4) * 8) * 2;
    const uint32_t offB = (uint32_t)(((lane & 7) + ((lane >> 4) & 1) * 8) * CP
                                     + ((lane >> 3) & 1) * 8) * 2;

    float4 acc[8] = {};

    const int wrow = tid >> 1, whalf = tid & 1;
    const int it = tid & 127, iarr = tid >> 7;
    const int irow = it >> 1, ihalf = it & 1;
    const bf16* isrc = iarr ? p.inTl : p.inTh;
    bf16* idst = iarr ? sIl : sIh;

    for (int chunk = 0; chunk < 8; chunk++) {
        const int k0 = chunk * 16;
        __syncthreads();
        size_t wg = (size_t)(mbase + wrow) * Hc + k0 + whalf * 8;
        *(uint4*)&sWh[wrow * CP + whalf * 8] = *(const uint4*)(p.Wh + wg);
        *(uint4*)&sWl[wrow * CP + whalf * 8] = *(const uint4*)(p.Wl + wg);
        *(uint4*)&idst[irow * CP + ihalf * 8] =
            *(const uint4*)(isrc + ((size_t)b * Nn + n0 + irow) * Hc + k0 + ihalf * 8);
        __syncthreads();

        uint32_t wh0, wh1, wh2, wh3, wl0, wl1, wl2, wl3;
        ldm4(wh0, wh1, wh2, wh3, sWh_u + offA);
        ldm4(wl0, wl1, wl2, wl3, sWl_u + offA);
        #pragma unroll
        for (int grp = 0; grp < 4; grp++) {
            const uint32_t go = (uint32_t)(grp * 16 * CP) * 2;
            uint32_t bh0, bh1, bh2, bh3, bl0, bl1, bl2, bl3;
            ldm4(bh0, bh1, bh2, bh3, sIh_u + go + offB);
            ldm4(bl0, bl1, bl2, bl3, sIl_u + go + offB);
            hmma(acc[2*grp], wh0, wh1, wh2, wh3, bh0, bh1);
            hmma(acc[2*grp], wh0, wh1, wh2, wh3, bl0, bl1);
            hmma(acc[2*grp], wl0, wl1, wl2, wl3, bh0, bh1);
            hmma(acc[2*grp+1], wh0, wh1, wh2, wh3, bh2, bh3);
            hmma(acc[2*grp+1], wh0, wh1, wh2, wh3, bl2, bl3);
            hmma(acc[2*grp+1], wl0, wl1, wl2, wl3, bh2, bh3);
        }
    }

    const int m_lo = mbase + warpM + g, m_hi = m_lo + 8;
    const float blo = p.bias[m_lo], bhi = p.bias[m_hi];
    #pragma unroll
    for (int nt = 0; nt < 8; nt++) {
        int n = n0 + nt * 8 + 2 * tg;
        float* d0 = &p.out[((size_t)b * Sc + m_lo) * Nn + n];
        float* d1 = &p.out[((size_t)b * Sc + m_hi) * Nn + n];
        float2 r0 = make_float2(acc[nt].x + blo, acc[nt].y + blo);
        float2 r1 = make_float2(acc[nt].z + bhi, acc[nt].w + bhi);
        if (p.accFlag) {
            float2 o0 = *(float2*)d0, o1 = *(float2*)d1;
            r0.x += o0.x; r0.y += o0.y; r1.x += o1.x; r1.y += o1.y;
        }
        *(float2*)d0 = r0;
        *(float2*)d1 = r1;
    }
}

__device__ void conv_dev(const ConvP& p, int bx, int by, char* buf) {
    float* Ws = (float*)buf;
    float* Ins = (float*)(buf + 16 * 68 * 4);
    const int tid = threadIdx.x;
    const int tx = tid & 15, ty = tid >> 4;
    const int col0 = bx * 64;
    const int b = col0 / Nn, n0 = col0 % Nn;
    const int m0 = by * 64;

    u64 accP[4][2] = {};

    for (int k0 = 0; k0 < p.K; k0 += 16) {
        for (int t = tid; t < 1024; t += 256) {
            int m = t >> 4, kk = t & 15;
            Ws[kk * 68 + m] = (m0 + m < p.M) ? p.W[(size_t)(m0 + m) * p.K + k0 + kk] : 0.f;
        }
        for (int t = tid; t < 1024; t += 256) {
            int kk = t >> 6, n = t & 63;
            int c = k0 + kk;
            Ins[kk * 68 + n] = p.srcs.p[c >> 5][(size_t)b * p.inBStride + (size_t)(c & 31) * Nn + n0 + n];
        }
        __syncthreads();
        #pragma unroll
        for (int kk = 0; kk < 16; kk++) {
            float4 wv = *(const float4*)&Ws[kk * 68 + ty * 4];
            u64 ip0 = *(const u64*)&Ins[kk * 68 + tx * 4];
            u64 ip1 = *(const u64*)&Ins[kk * 68 + tx * 4 + 2];
            float wa[4] = {wv.x, wv.y, wv.z, wv.w};
            #pragma unroll
            for (int u = 0; u < 4; u++) {
                u64 wp = splat2(wa[u]);
                accP[u][0] = fma2(wp, ip0, accP[u][0]);
                accP[u][1] = fma2(wp, ip1, accP[u][1]);
            }
        }
        __syncthreads();
    }
    float lsum = 0.f, lsum2 = 0.f;
    #pragma unroll
    for (int u = 0; u < 4; u++) {
        int m = m0 + ty * 4 + u;
        if (m >= p.M) break;
        float bm = p.bias[m];
        float4 r;
        upk2(accP[u][0], r.x, r.y);
        upk2(accP[u][1], r.z, r.w);
        r.x += bm; r.y += bm; r.z += bm; r.w += bm;
        float* dst = &p.out[(size_t)b * p.outBStride + (size_t)m * Nn + n0 + tx * 4];
        if (p.iden) {
            float4 o = *(const float4*)&p.iden[(size_t)b * p.outBStride + (size_t)m * Nn + n0 + tx * 4];
            r.x += o.x; r.y += o.y; r.z += o.z; r.w += o.w;
        }
        if (p.accFlag) {
            float4 o = *(float4*)dst;
            r.x += o.x; r.y += o.y; r.z += o.z; r.w += o.w;
        }
        *(float4*)dst = r;
        if (p.redOut) {
            lsum += r.x + r.y + r.z + r.w;
            lsum2 += r.x * r.x + r.y * r.y + r.z * r.z + r.w * r.w;
        }
    }
    if (p.redOut) {
        float ts = blockReduceSum(lsum);
        __syncthreads();
        float ts2 = blockReduceSum(lsum2);
        if (tid == 0) {
            atomicAdd(&p.redOut[b * 2], ts);
            atomicAdd(&p.redOut[b * 2 + 1], ts2);
        }
    }
}

// ================= fat kernels =================
// Phase A/B: z<3 -> SpMM hop across the 3 graphs; z==3 -> gated TCN stage.
__global__ void __launch_bounds__(256) phaseAB_k(SpmmB sa, GatedP gp) {
    __shared__ __align__(16) char buf[30720];
    if (blockIdx.z < 3) spmm_dev(sa, blockIdx.x, blockIdx.y, blockIdx.z, buf);
    else gated_dev(gp, blockIdx.y * 32 + blockIdx.x, buf);
}

// Phase C: blocks [0,512) -> skip conv; [512,768) -> mixprop MLP conv (+LN stats).
__global__ void __launch_bounds__(256) phaseC_k(SkipP sp, ConvP cp) {
    __shared__ __align__(16) char buf[18432];
    int blk = blockIdx.x;
    if (blk < 512) skip_dev(sp, blk & 255, blk >> 8, buf);
    else conv_dev(cp, blk - 512, 0, buf);
}

// plain conv kernel for final skipE/end
__global__ void __launch_bounds__(256) conv1x1_k(ConvP cp) {
    __shared__ __align__(16) char buf[8704];
    conv_dev(cp, blockIdx.x, blockIdx.y, buf);
}

// ---------------- layernorm apply ----------------
__global__ void ln_apply_k(const float* __restrict__ w, const float* __restrict__ bparm,
                           const float* __restrict__ red) {
    int i = blockIdx.x * 256 + threadIdx.x;
    if (i >= NEL) return;
    int b = i >> 16;
    int cn = i & (Ee * Nn - 1);
    float inv = 1.0f / (Ee * Nn);
    float mu = red[b * 2] * inv;
    float var = red[b * 2 + 1] * inv - mu * mu;
    float val = (g_xacc[i] - mu) * rsqrtf(var + EPSV) * w[cn] + bparm[cn];
    val = fmaxf(val, 0.f);
    g_x[i] = val;
    bf16 h, l; bsplit(val, h, l);
    g_sxHi[i] = h;
    int n = i & (Nn - 1);
    int c = (i >> 11) & 31;
    size_t o = ((size_t)b * Nn + n) * Hc + c;
    g_in1Th[o] = h;
    g_in1Tl[o] = l;
}

// ---------------- host orchestration ----------------
extern "C" void kernel_launch(void* const* d_in, const int* in_sizes, int n_in,
                              void* d_out, int out_size) {
    (void)in_sizes; (void)n_in; (void)out_size;
    const float* in_x  = (const float*)d_in[0];
    const float* dyG   = (const float*)d_in[1];
    const float* stG   = (const float*)d_in[2];
    const float* spE   = (const float*)d_in[3];
    const float* tdE   = (const float*)d_in[4];
    const float* twE   = (const float*)d_in[5];
    const float* encWf = (const float*)d_in[6];
    const float* encbf = (const float*)d_in[7];
    const float* encWg = (const float*)d_in[8];
    const float* encbg = (const float*)d_in[9];
    const float* skW   = (const float*)d_in[10];
    const float* skb   = (const float*)d_in[11];
    const float* nw    = (const float*)d_in[12];
    const float* nb    = (const float*)d_in[13];
    const float* gW[3] = {(const float*)d_in[14], (const float*)d_in[16], (const float*)d_in[18]};
    const float* gb[3] = {(const float*)d_in[15], (const float*)d_in[17], (const float*)d_in[19]};
    const float* seW   = (const float*)d_in[20];
    const float* seb   = (const float*)d_in[21];
    const float* eW    = (const float*)d_in[22];
    const float* eb    = (const float*)d_in[23];
    float* outp = (float*)d_out;

    float *px, *pxacc, *pskip, *prss, *prsd, *pcsd, *ph1g, *ph2g, *pgWc, *pgbc, *predL;
    cudaGetSymbolAddress((void**)&px,    g_x);
    cudaGetSymbolAddress((void**)&pxacc, g_xacc);
    cudaGetSymbolAddress((void**)&pskip, g_skip);
    cudaGetSymbolAddress((void**)&prss,  g_rs_s);
    cudaGetSymbolAddress((void**)&prsd,  g_rs_d);
    cudaGetSymbolAddress((void**)&pcsd,  g_cs_d);
    cudaGetSymbolAddress((void**)&ph1g,  g_h1g);
    cudaGetSymbolAddress((void**)&ph2g,  g_h2g);
    cudaGetSymbolAddress((void**)&pgWc,  g_gWc);
    cudaGetSymbolAddress((void**)&pgbc,  g_gbc);
    cudaGetSymbolAddress((void**)&predL, g_redL);
    bf16 *pAhi, *pShi, *psxHi, *ps1Hi;
    cudaGetSymbolAddress((void**)&pAhi,  g_Ahi);
    cudaGetSymbolAddress((void**)&pShi,  g_Shi);
    cudaGetSymbolAddress((void**)&psxHi, g_sxHi);
    cudaGetSymbolAddress((void**)&ps1Hi, g_s1Hi);
    bf16 *pin1Th, *pin1Tl, *phidTh, *phidTl, *phid2Th, *phid2Tl;
    cudaGetSymbolAddress((void**)&pin1Th, g_in1Th);
    cudaGetSymbolAddress((void**)&pin1Tl, g_in1Tl);
    cudaGetSymbolAddress((void**)&phidTh, g_hidTh);
    cudaGetSymbolAddress((void**)&phidTl, g_hidTl);
    cudaGetSymbolAddress((void**)&phid2Th, g_hid2Th);
    cudaGetSymbolAddress((void**)&phid2Tl, g_hid2Tl);
    bf16 *peWfh, *peWfl, *peWgh, *peWgl, *pskWh, *pskWl;
    cudaGetSymbolAddress((void**)&peWfh, g_eWfh);
    cudaGetSymbolAddress((void**)&peWfl, g_eWfl);
    cudaGetSymbolAddress((void**)&peWgh, g_eWgh);
    cudaGetSymbolAddress((void**)&peWgl, g_eWgl);
    cudaGetSymbolAddress((void**)&pskWh, g_skWh);
    cudaGetSymbolAddress((void**)&pskWl, g_skWl);

    // ---- prep ----
    copy_split_k<<<(NEL / 4 + 255) / 256, 256>>>(px, in_x);
    init_den_k<<<(Bb * Nn + 255) / 256, 256>>>();
    prepA_k<<<dim3(Nn / 64, Nn / 64, Bb), 256>>>(dyG);
    prepS_k<<<dim3(Nn / 64, Nn / 64), 256>>>(stG);
    cvt_k<<<(6 * Hc * Hc / 4 + 255) / 256, 256>>>(encWf, peWfh, peWfl, 6 * Hc * Hc / 4);
    cvt_k<<<(6 * Hc * Hc / 4 + 255) / 256, 256>>>(encWg, peWgh, peWgl, 6 * Hc * Hc / 4);
    cvt_k<<<(3 * Sc * Hc / 4 + 255) / 256, 256>>>(skW, pskWh, pskWl, 3 * Sc * Hc / 4);
    embT_k<<<(Bb * 96 * (Nn / 4) + 255) / 256, 256>>>(spE, tdE, twE);
    combW_k<<<(3 * 32 * 224 + 255) / 256, 256>>>(gW[0], gW[1], gW[2]);
    combB_k<<<1, 96>>>(gb[0], gb[1], gb[2]);

    SpmmB ab;
    ab.A[0] = pShi; ab.abst[0] = 0;            ab.den[0] = prss; ab.denB[0] = 0;
    ab.A[1] = pAhi; ab.abst[1] = (u64)Nn * Nn; ab.den[1] = prsd; ab.denB[1] = Nn;
    ab.A[2] = pAhi; ab.abst[2] = (u64)Nn * Nn; ab.den[2] = pcsd; ab.denB[2] = Nn;

    const dim3 fatGrid(Nn / 64, Bb, 4);
    for (int i = 0; i < 3; i++) {
        // ---- Phase A: hop-1 (3 graphs) || gated-1 ----
        SpmmB a1 = ab;
        for (int g = 0; g < 3; g++) {
            a1.H[g] = psxHi;
            a1.hout[g] = ph1g + (size_t)g * NEL;
            a1.sOut[g] = ps1Hi + (size_t)g * NEL;
        }
        a1.writeSplit = 1;
        GatedP g1;
        g1.inTh = pin1Th; g1.inTl = pin1Tl;
        g1.Wfh = peWfh + (size_t)(i * 2 + 0) * Hc * Hc;
        g1.Wfl = peWfl + (size_t)(i * 2 + 0) * Hc * Hc;
        g1.Wgh = peWgh + (size_t)(i * 2 + 0) * Hc * Hc;
        g1.Wgl = peWgl + (size_t)(i * 2 + 0) * Hc * Hc;
        g1.bf_ = encbf + (i * 2 + 0) * Hc; g1.bg_ = encbg + (i * 2 + 0) * Hc;
        g1.outTh = phidTh; g1.outTl = phidTl;
        phaseAB_k<<<fatGrid, 256>>>(a1, g1);

        // ---- Phase B: hop-2 (3 graphs) || gated-2 ----
        SpmmB a2 = ab;
        for (int g = 0; g < 3; g++) {
            a2.H[g] = ps1Hi + (size_t)g * NEL;
            a2.hout[g] = ph2g + (size_t)g * NEL;
            a2.sOut[g] = ps1Hi + (size_t)g * NEL;  // unused
        }
        a2.writeSplit = 0;
        GatedP g2;
        g2.inTh = phidTh; g2.inTl = phidTl;
        g2.Wfh = peWfh + (size_t)(i * 2 + 1) * Hc * Hc;
        g2.Wfl = peWfl + (size_t)(i * 2 + 1) * Hc * Hc;
        g2.Wgh = peWgh + (size_t)(i * 2 + 1) * Hc * Hc;
        g2.Wgl = peWgl + (size_t)(i * 2 + 1) * Hc * Hc;
        g2.bf_ = encbf + (i * 2 + 1) * Hc; g2.bg_ = encbg + (i * 2 + 1) * Hc;
        g2.outTh = phid2Th; g2.outTl = phid2Tl;
        phaseAB_k<<<fatGrid, 256>>>(a2, g2);

        // ---- Phase C: skip conv || mixprop MLP (+LN stats) ----
        SkipP sp;
        sp.inTh = phid2Th; sp.inTl = phid2Tl;
        sp.Wh = pskWh + (size_t)i * Sc * Hc; sp.Wl = pskWl + (size_t)i * Sc * Hc;
        sp.bias = skb + i * Sc; sp.out = pskip; sp.accFlag = (i > 0);
        ConvP cp;
        cp.srcs.p[0] = px;
        cp.srcs.p[1] = ph1g + 0 * NEL; cp.srcs.p[2] = ph2g + 0 * NEL;
        cp.srcs.p[3] = ph1g + 1 * NEL; cp.srcs.p[4] = ph2g + 1 * NEL;
        cp.srcs.p[5] = ph1g + 2 * NEL; cp.srcs.p[6] = ph2g + 2 * NEL;
        cp.srcs.p[7] = px;
        cp.inBStride = Ee * Nn;
        cp.W = pgWc + (size_t)i * 32 * 224; cp.bias = pgbc + i * 32;
        cp.M = Ee; cp.K = 224;
        cp.out = pxacc; cp.outBStride = Ee * Nn;
        cp.accFlag = 0; cp.iden = px; cp.redOut = predL + i * Bb * 2;
        phaseC_k<<<768, 256>>>(sp, cp);

        // ---- layernorm + relu ----
        ln_apply_k<<<NEL / 256, 256>>>(nw + (size_t)i * Ee * Nn, nb + (size_t)i * Ee * Nn,
                                       predL + i * Bb * 2);
    }
    // ---- skip end + output ----
    ConvP se;
    se.srcs.p[0] = px;
    for (int s = 1; s < 8; s++) se.srcs.p[s] = px;
    se.inBStride = Ee * Nn;
    se.W = seW; se.bias = seb; se.M = Sc; se.K = Ee;
    se.out = pskip; se.outBStride = Sc * Nn;
    se.accFlag = 1; se.iden = nullptr; se.redOut = nullptr;
    conv1x1_k<<<dim3(Bb * Nn / 64, 4), 256>>>(se);
    ConvP ce;
    for (int s = 0; s < 8; s++) ce.srcs.p[s] = pskip + (size_t)s * 32 * Nn;
    ce.inBStride = Sc * Nn;
    ce.W = eW; ce.bias = eb; ce.M = Tt; ce.K = Sc;
    ce.out = outp; ce.outBStride = Tt * Nn;
    ce.accFlag = 0; ce.iden = nullptr; ce.redOut = nullptr;
    conv1x1_k<<<dim3(Bb * Nn / 64, 1), 256>>>(ce);
}